// round 8
// baseline (speedup 1.0000x reference)
#include <cuda_runtime.h>
#include <cuda_bf16.h>
#include <math.h>
#include <stdint.h>

#define B_  512
#define S_  512
#define DI_ 256
#define DO_ 256

// Packed Wh A-fragments, half-M granular:
// [g2(=t*8+kc)][hf(2)][w(8)][ks(4)*32+lane] float4; 4096*2*8*128 = 8,388,608 float4 = 134MB.
__device__ float4 WhP_g[(size_t)S_ * 8 * 2 * 8 * 128];

// ---------------- helpers ----------------

__device__ __forceinline__ void cpasync16(void* smem_dst, const void* gsrc) {
    unsigned saddr = (unsigned)__cvta_generic_to_shared(smem_dst);
    asm volatile("cp.async.cg.shared.global [%0], [%1], 16;\n" :: "r"(saddr), "l"(gsrc));
}
__device__ __forceinline__ void cp_commit() { asm volatile("cp.async.commit_group;\n"); }
template <int N> __device__ __forceinline__ void cp_wait() {
    asm volatile("cp.async.wait_group %0;\n" :: "n"(N));
}
__device__ __forceinline__ unsigned f2u(float f) { return __float_as_uint(f); }
__device__ __forceinline__ float fast_tanh(float x) {
    float e = __expf(2.0f * x);
    return 1.0f - __fdividef(2.0f, e + 1.0f);
}
__device__ __forceinline__ uint32_t smem_u32(const void* p) {
    return (uint32_t)__cvta_generic_to_shared(p);
}

__device__ __forceinline__ void mma_tf32(float c[4],
                                         unsigned a0, unsigned a1, unsigned a2, unsigned a3,
                                         unsigned b0, unsigned b1) {
    asm volatile(
        "mma.sync.aligned.m16n8k8.row.col.f32.tf32.tf32.f32 "
        "{%0,%1,%2,%3}, {%4,%5,%6,%7}, {%8,%9}, {%0,%1,%2,%3};\n"
        : "+f"(c[0]), "+f"(c[1]), "+f"(c[2]), "+f"(c[3])
        : "r"(a0), "r"(a1), "r"(a2), "r"(a3), "r"(b0), "r"(b1));
}

#define LDSM_X4(r0, r1, r2, r3, addr) \
    asm volatile("ldmatrix.sync.aligned.m8n8.x4.shared.b16 {%0,%1,%2,%3}, [%4];" \
                 : "=r"(r0), "=r"(r1), "=r"(r2), "=r"(r3) : "r"(addr))

#define CLUSTER_ARRIVE() asm volatile("barrier.cluster.arrive.aligned;" ::: "memory")
#define CLUSTER_WAIT()   asm volatile("barrier.cluster.wait.aligned;" ::: "memory")

__device__ __forceinline__ uint32_t mapa_peer(uint32_t local_addr, uint32_t peer_rank) {
    uint32_t r;
    asm volatile("mapa.shared::cluster.u32 %0, %1, %2;" : "=r"(r) : "r"(local_addr), "r"(peer_rank));
    return r;
}
__device__ __forceinline__ void st_cluster_f32(uint32_t addr, float v) {
    asm volatile("st.shared::cluster.f32 [%0], %1;" :: "r"(addr), "f"(v) : "memory");
}

// ---------------- Phase 0: pack Wh, half-M fragment layout ----------------
// grid (kc=8, t=512), 256 thr; CTA covers k rows [kc*32, kc*32+32).
// For half hf, warp w (m=16 cols): m0 = hf*128 + w*16 + (lane>>2), kk = kc*32 + ks*8 + (lane&3)
//   v = { A[m0][kk], A[m0+8][kk], A[m0][kk+4], A[m0+8][kk+4] },  A = Wh^T (A[m][k] = Wh[k][m]).

__global__ __launch_bounds__(256, 1) void prepack_wh(const float* __restrict__ Wh)
{
    __shared__ float tile[32 * 260];
    const int kc  = blockIdx.x;
    const int t   = blockIdx.y;
    const int tid = threadIdx.x;
    const float* src = Wh + (size_t)t * (DO_ * DO_) + (size_t)kc * 32 * DO_;

#pragma unroll
    for (int j = 0; j < 8; j++) {
        int idx = tid + j * 256;
        int r = idx >> 6, q = idx & 63;
        *(float4*)&tile[r * 260 + q * 4] = *(const float4*)&src[r * DO_ + q * 4];
    }
    __syncthreads();

    const size_t g2 = (size_t)t * 8 + kc;
#pragma unroll
    for (int j = 0; j < 8; j++) {
        int idx  = tid + j * 256;                 // 0..2047
        int lane = idx & 31;                      // bits 0-4
        int ks   = (idx >> 5) & 3;                // bits 5-6
        int w    = (idx >> 7) & 7;                // bits 7-9
        int hf   = (idx >> 10) & 1;               // bit 10
        int kloc = ks * 8 + (lane & 3);
        int m0   = hf * 128 + w * 16 + (lane >> 2);
        float4 v;
        v.x = tile[kloc * 260 + m0];
        v.y = tile[kloc * 260 + m0 + 8];
        v.z = tile[(kloc + 4) * 260 + m0];
        v.w = tile[(kloc + 4) * 260 + m0 + 8];
        WhP_g[((g2 * 2 + hf) * 8 + w) * 128 + ks * 32 + lane] = v;
    }
}

// ---------------- Phase 1: Z[b,t,:] = x[b,t,:] @ Wx[t]  (unchanged, 2 CTAs/SM) ----------------

#define P1_AS  (128 * 36)
#define P1_BS  (32 * 132)
#define P1_SMEM ((2 * P1_AS + 2 * P1_BS) * 4)

__global__ __launch_bounds__(256, 2) void rnn_phase1(
    const float* __restrict__ x, const float* __restrict__ Wx, float* __restrict__ out)
{
    extern __shared__ float sm[];
    float* As[2] = { sm, sm + P1_AS };
    float* Bs[2] = { sm + 2 * P1_AS, sm + 2 * P1_AS + P1_BS };

    const int t      = blockIdx.z;
    const int m_base = blockIdx.y * 128;
    const int n_base = blockIdx.x * 128;
    const int tid    = threadIdx.x;
    const int warp   = tid >> 5, lane = tid & 31;
    const int wm     = warp & 3, wn = warp >> 2;
    const int grp    = lane >> 2, tig = lane & 3;

    float acc[2][8][4];
#pragma unroll
    for (int mt = 0; mt < 2; mt++)
#pragma unroll
        for (int nt = 0; nt < 8; nt++)
#pragma unroll
            for (int i = 0; i < 4; i++) acc[mt][nt][i] = 0.f;

    auto loadA = [&](int kc, int buf) {
#pragma unroll
        for (int j = 0; j < 4; j++) {
            int i = tid + j * 256;
            int r = i >> 3, q = i & 7;
            cpasync16(&As[buf][r * 36 + q * 4],
                      x + ((m_base + r) * S_ + t) * DI_ + kc * 32 + q * 4);
        }
        cp_commit();
    };
    auto loadB = [&](int kc, int buf) {
#pragma unroll
        for (int j = 0; j < 4; j++) {
            int i = tid + j * 256;
            int k = i >> 5, q = i & 31;
            cpasync16(&Bs[buf][k * 132 + q * 4],
                      Wx + t * (DI_ * DO_) + (kc * 32 + k) * DO_ + n_base + q * 4);
        }
        cp_commit();
    };

    loadA(0, 0); loadB(0, 0);
    loadA(1, 1); loadB(1, 1);

    for (int kc = 0; kc < 8; kc++) {
        if (kc < 7) cp_wait<2>(); else cp_wait<0>();
        __syncthreads();
        const int buf = kc & 1;
        const float* A = As[buf];
        const float* Bsm = Bs[buf];
#pragma unroll
        for (int ks = 0; ks < 4; ks++) {
            const int k = ks * 8;
            unsigned a[2][4];
#pragma unroll
            for (int mt = 0; mt < 2; mt++) {
                const int rb = wm * 32 + mt * 16;
                a[mt][0] = f2u(A[(rb + grp)     * 36 + k + tig]);
                a[mt][1] = f2u(A[(rb + grp + 8) * 36 + k + tig]);
                a[mt][2] = f2u(A[(rb + grp)     * 36 + k + 4 + tig]);
                a[mt][3] = f2u(A[(rb + grp + 8) * 36 + k + 4 + tig]);
            }
#pragma unroll
            for (int nt = 0; nt < 8; nt++) {
                const int cb = wn * 64 + nt * 8 + grp;
                unsigned b0 = f2u(Bsm[(k + tig)     * 132 + cb]);
                unsigned b1 = f2u(Bsm[(k + 4 + tig) * 132 + cb]);
#pragma unroll
                for (int mt = 0; mt < 2; mt++)
                    mma_tf32(acc[mt][nt], a[mt][0], a[mt][1], a[mt][2], a[mt][3], b0, b1);
            }
        }
        __syncthreads();
        if (kc + 2 < 8) { loadA(kc + 2, buf); loadB(kc + 2, buf); }
    }

#pragma unroll
    for (int mt = 0; mt < 2; mt++) {
#pragma unroll
        for (int nt = 0; nt < 8; nt++) {
            const int row = m_base + wm * 32 + mt * 16 + grp;
            const int col = n_base + wn * 64 + nt * 8 + 2 * tig;
            const int g0 = (row * S_ + t) * DO_ + col;
            float2 v0; v0.x = acc[mt][nt][0]; v0.y = acc[mt][nt][1];
            *(float2*)&out[g0] = v0;
            const int g1 = ((row + 8) * S_ + t) * DO_ + col;
            float2 v1; v1.x = acc[mt][nt][2]; v1.y = acc[mt][nt][3];
            *(float2*)&out[g1] = v1;
        }
    }
}

// ---------------- Phase 2 v6: 2-CTA clusters, M-split, hidden h-exchange ----------------
// 32 clusters x 2 CTAs; cluster owns 16 batch rows, CTA rank r owns out cols [128r,128r+128).
// Per step: CTA processes its OWN-k chunks first (kc = (j+4r)&7, j=0..3 -> own h half),
// cluster-waits for the peer's h half, then peer-k chunks (j=4..7). Epilogue writes h
// locally + into the peer's next-step buffer via st.shared::cluster, then cluster-arrives.
// A-frags: LDG.128 register ring (4 slots, static indices, distance-3 prefetch).

#define P2_HPAD 260

__global__ __launch_bounds__(256, 1) __cluster_dims__(2, 1, 1)
void rnn_phase2(float* __restrict__ out)
{
    __shared__ __align__(16) float hs[2][16 * P2_HPAD];

    const int tid  = threadIdx.x;
    const int w    = tid >> 5, lane = tid & 31;
    const int grp  = lane >> 2, tig = lane & 3;
    const unsigned rank = blockIdx.x & 1;
    const int brow = (blockIdx.x >> 1) * 16;
    const int mloc = w * 16 + grp;            // local col within half (plus +8)
    const int mglob = (int)rank * 128 + mloc; // global out col

    for (int i = tid; i < 16 * P2_HPAD; i += 256) { hs[0][i] = 0.f; hs[1][i] = 0.f; }
    __syncthreads();

    const uint32_t hb[2] = { smem_u32(hs[0]), smem_u32(hs[1]) };
    const uint32_t pb[2] = { mapa_peer(hb[0], rank ^ 1), mapa_peer(hb[1], rank ^ 1) };
    const uint32_t lm0 = (uint32_t)((lane & 7) * P2_HPAD + (lane >> 3) * 4) * 4;

    float4 A[4][4];   // ring [slot][ks] — static indices only

    auto ldA = [&](int p, int slot) {        // slot compile-time at every call site
        const int kcp = (((p & 7) + 4 * (int)rank) & 7);
        const size_t base = (((size_t)((p >> 3) * 8 + kcp) * 2 + rank) * 8 + w) * 128 + lane;
#pragma unroll
        for (int ks = 0; ks < 4; ks++)
            A[slot][ks] = __ldg(&WhP_g[base + ks * 32]);
    };

    ldA(0, 0); ldA(1, 1); ldA(2, 2);

    float acc[2][4];   // [nt][i]
    float z[2][4];

    for (int t = 0; t < S_; t++) {
        const uint32_t hrd = hb[t & 1];
        float* hwr = hs[(t & 1) ^ 1];
        const uint32_t pwr = pb[(t & 1) ^ 1];

#pragma unroll
        for (int nt = 0; nt < 2; nt++)
#pragma unroll
            for (int i = 0; i < 4; i++) acc[nt][i] = 0.f;

        // Z prefetch (independent of h)
#pragma unroll
        for (int nt = 0; nt < 2; nt++) {
            const int r0 = nt * 8 + 2 * tig;
            z[nt][0] = __ldg(&out[((size_t)(brow + r0)     * S_ + t) * DO_ + mglob]);
            z[nt][1] = __ldg(&out[((size_t)(brow + r0 + 1) * S_ + t) * DO_ + mglob]);
            z[nt][2] = __ldg(&out[((size_t)(brow + r0)     * S_ + t) * DO_ + mglob + 8]);
            z[nt][3] = __ldg(&out[((size_t)(brow + r0 + 1) * S_ + t) * DO_ + mglob + 8]);
        }

#define CHUNK_BODY(J)                                                                   \
        {                                                                               \
            const int kc = (((J) + 4 * (int)rank) & 7);                                 \
            const uint32_t ka = hrd + (uint32_t)(kc * 128);                             \
            uint32_t b00,b01,b02,b03,b04,b05,b06,b07;                                   \
            uint32_t b10,b11,b12,b13,b14,b15,b16,b17;                                   \
            LDSM_X4(b00,b01,b02,b03, ka + lm0);                                         \
            LDSM_X4(b04,b05,b06,b07, ka + lm0 + 64);                                    \
            LDSM_X4(b10,b11,b12,b13, ka + lm0 + 8 * P2_HPAD * 4);                       \
            LDSM_X4(b14,b15,b16,b17, ka + lm0 + 8 * P2_HPAD * 4 + 64);                  \
            { const float4 af = A[(J) & 3][0];                                          \
              mma_tf32(acc[0], f2u(af.x),f2u(af.y),f2u(af.z),f2u(af.w), b00, b01);      \
              mma_tf32(acc[1], f2u(af.x),f2u(af.y),f2u(af.z),f2u(af.w), b10, b11); }    \
            { const float4 af = A[(J) & 3][1];                                          \
              mma_tf32(acc[0], f2u(af.x),f2u(af.y),f2u(af.z),f2u(af.w), b02, b03);      \
              mma_tf32(acc[1], f2u(af.x),f2u(af.y),f2u(af.z),f2u(af.w), b12, b13); }    \
            { const float4 af = A[(J) & 3][2];                                          \
              mma_tf32(acc[0], f2u(af.x),f2u(af.y),f2u(af.z),f2u(af.w), b04, b05);      \
              mma_tf32(acc[1], f2u(af.x),f2u(af.y),f2u(af.z),f2u(af.w), b14, b15); }    \
            { const float4 af = A[(J) & 3][3];                                          \
              mma_tf32(acc[0], f2u(af.x),f2u(af.y),f2u(af.z),f2u(af.w), b06, b07);      \
              mma_tf32(acc[1], f2u(af.x),f2u(af.y),f2u(af.z),f2u(af.w), b16, b17); }    \
            { const int p2 = t * 8 + (J) + 3;                                           \
              if (p2 < S_ * 8) ldA(p2, ((J) + 3) & 3); }                                \
        }

        // own-k half (h data produced locally last step)
        CHUNK_BODY(0) CHUNK_BODY(1) CHUNK_BODY(2) CHUNK_BODY(3)

        if (t > 0) CLUSTER_WAIT();   // peer's h_{t-1} half has landed

        // peer-k half
        CHUNK_BODY(4) CHUNK_BODY(5) CHUNK_BODY(6) CHUNK_BODY(7)
#undef CHUNK_BODY

        // epilogue: h = tanh(Z + Wh^T h); write gmem + local + peer next-step buffers
#pragma unroll
        for (int nt = 0; nt < 2; nt++) {
            const int r0 = nt * 8 + 2 * tig;
            const float h0 = fast_tanh(z[nt][0] + acc[nt][0]);
            const float h1 = fast_tanh(z[nt][1] + acc[nt][1]);
            const float h2 = fast_tanh(z[nt][2] + acc[nt][2]);
            const float h3 = fast_tanh(z[nt][3] + acc[nt][3]);

            out[((size_t)(brow + r0)     * S_ + t) * DO_ + mglob]     = h0;
            out[((size_t)(brow + r0 + 1) * S_ + t) * DO_ + mglob]     = h1;
            out[((size_t)(brow + r0)     * S_ + t) * DO_ + mglob + 8] = h2;
            out[((size_t)(brow + r0 + 1) * S_ + t) * DO_ + mglob + 8] = h3;

            hwr[r0 * P2_HPAD + mglob]           = h0;
            hwr[(r0 + 1) * P2_HPAD + mglob]     = h1;
            hwr[r0 * P2_HPAD + mglob + 8]       = h2;
            hwr[(r0 + 1) * P2_HPAD + mglob + 8] = h3;

            st_cluster_f32(pwr + (uint32_t)(r0 * P2_HPAD + mglob) * 4,           h0);
            st_cluster_f32(pwr + (uint32_t)((r0 + 1) * P2_HPAD + mglob) * 4,     h1);
            st_cluster_f32(pwr + (uint32_t)(r0 * P2_HPAD + mglob + 8) * 4,       h2);
            st_cluster_f32(pwr + (uint32_t)((r0 + 1) * P2_HPAD + mglob + 8) * 4, h3);
        }

        CLUSTER_ARRIVE();    // releases DSMEM stores of h_t; licenses peer's next write
        __syncthreads();     // local h_t visible to own warps
    }

    CLUSTER_WAIT();          // balance final arrive; all DSMEM traffic drained
}

// ---------------- launch ----------------

extern "C" void kernel_launch(void* const* d_in, const int* in_sizes, int n_in,
                              void* d_out, int out_size)
{
    const float* x  = (const float*)d_in[0];   // [B, S, DI]
    const float* Wx = (const float*)d_in[1];   // [S, DI, DO]
    const float* Wh = (const float*)d_in[2];   // [S, DO, DO]
    float* out = (float*)d_out;                // [B, S, DO]

    cudaFuncSetAttribute(rnn_phase1, cudaFuncAttributeMaxDynamicSharedMemorySize, P1_SMEM);

    prepack_wh<<<dim3(8, S_), 256>>>(Wh);

    dim3 g1(DO_ / 128, B_ / 128, S_);
    rnn_phase1<<<g1, 256, P1_SMEM>>>(x, Wx, out);

    rnn_phase2<<<B_ / 16 * 2, 256>>>(out);   // 64 CTAs = 32 clusters of 2
}